// round 6
// baseline (speedup 1.0000x reference)
#include <cuda_runtime.h>
#include <math.h>

// Problem constants (must match reference)
#define BB 16
#define HH 120
#define WW 160
#define DD 401              // int(8000/20)+1
#define WT 4                // w-tile per block (== one float4 of depth per row)
#define NT 384              // 12 warps -> 5 blocks/SM -> one full wave for 640 blocks
#define NV4 ((WT * DD) / 4) // 401 float4 in the block's output span
#define DEPTH_MAX 8000.0f
#define INV_BIN   (1.0f / 20.0f)
#define BIN_SIZE  20.0f
#define ZERO_EPS  1e-06f
#define SIG_EPS   (0.5f + 1e-08f)

// fp32 sparsity: the Gaussian underflows to exactly 0 unless |k*20 - d| < ~7.2;
// bins are 20 apart -> only the rounded-nearest bin k = round(d/20) can be
// nonzero. For valid d in (eps, 8000], k in [0,400]: no clamp. (d>eps && d<=max)
// also rejects NaN/Inf.
//
// Frame (tied-best from r3/r5): block owns out[b, w0..w0+3, :] exclusively;
// zero that span in GMEM (overlapped with the depth load), bar.sync
// (exec + membar.cta), then fire-and-forget RED.E.ADD.F32 scatter. This round:
// depth read as ONE LDG.128 per row (thread t < 120 owns row t's 4 pixels),
// minimizing warp-instructions and MLP_p1 (spread-model floor class).

__global__ void __launch_bounds__(NT)
dim_hist_kernel(const float* __restrict__ depth, float* __restrict__ out)
{
    const int blk = blockIdx.x;              // 0 .. 639
    const int b   = blk / (WW / WT);
    const int w0  = (blk - b * (WW / WT)) * WT;
    const int tid = threadIdx.x;

    // ---- one LDG.128 per row, issued first: latency overlaps zero stores ----
    float4 d4 = make_float4(-1.f, -1.f, -1.f, -1.f);
    if (tid < HH)
        d4 = *(const float4*)(depth + ((size_t)b * HH + tid) * WW + w0);

    // ---- zero this block's private output span: 401 STG.128 ----
    float* ospan = out + ((size_t)b * WW + w0) * DD;             // 16B-aligned
    float4* o4 = (float4*)ospan;
    const float4 z4 = make_float4(0.f, 0.f, 0.f, 0.f);
    o4[tid] = z4;                                 // tid < 384 < 401 always
    if (tid + NT < NV4) o4[tid + NT] = z4;        // threads 0..16 cover the rest

    __syncthreads();   // exec + membar.cta: zeros visible before our atomics

    const float inv_sig = 1.0f / SIG_EPS;                 // 1/(sigma+eps)
    const float norm    = 0.3989422804014327f * inv_sig;  // 1/((sigma+eps)*sqrt(2pi))

    // ---- scatter: 4 pixels per loading thread; REDGs have no consumers ----
    if (tid < HH) {
        const float dv[WT] = {d4.x, d4.y, d4.z, d4.w};
        #pragma unroll
        for (int wi = 0; wi < WT; ++wi) {
            float d = dv[wi];
            if (d > ZERO_EPS && d <= DEPTH_MAX) {
                int k   = __float2int_rn(d * INV_BIN);        // nearest bin, [0,400]
                float z = ((float)k * BIN_SIZE - d) * inv_sig;
                float g = __expf(-0.5f * z * z) * norm;
                if (g != 0.0f) atomicAdd(&ospan[wi * DD + k], g);  // RED.E.ADD.F32
            }
        }
    }
}

extern "C" void kernel_launch(void* const* d_in, const int* in_sizes, int n_in,
                              void* d_out, int out_size)
{
    const float* depth = (const float*)d_in[0];
    float* out = (float*)d_out;
    dim_hist_kernel<<<(BB * WW) / WT, NT>>>(depth, out);
}